// round 1
// baseline (speedup 1.0000x reference)
#include <cuda_runtime.h>
#include <cuda_bf16.h>
#include <cstdint>
#include <cstddef>

// Problem constants (fixed by the dataset)
#define TT   2048
#define HH   1024
#define EE   1024
#define VV   32000
#define G4   4096      // 4*H
#define NCTA 128       // persistent scan CTAs (<= SM count, single wave guaranteed)
#define UPC  8         // hidden units per CTA (NCTA*UPC == HH)

// ---------------- scratch (no allocations allowed) ----------------
__device__ float g_xg[(size_t)TT * G4];          // 33.5 MB  [T,4H]
__device__ float g_hs[(size_t)TT * HH];          //  8.4 MB  [T,H]
__device__ float g_scores[(size_t)TT * VV];      // 262 MB   [T,V]
__device__ float g_hbuf[2][HH];                  // h ping-pong
__device__ unsigned g_arrive;                    // monotonic barrier counters
__device__ unsigned g_release;                   // (wrap-safe, no reset needed)

// =================================================================
// Classic 128x128x8 SGEMM:  C[m][n] = sum_k A[m][k]*B[n][k] (+bias)
// A rows optionally gathered (embedding lookup fused into the load).
// =================================================================
__global__ void __launch_bounds__(256) sgemm_tn(
    const float* __restrict__ A, const float* __restrict__ B,
    const float* __restrict__ bias1, const float* __restrict__ bias2,
    float* __restrict__ C, int M, int N, int K,
    const int* __restrict__ gather)
{
    __shared__ float As[8][128];
    __shared__ float Bs[8][128];
    const int tid = threadIdx.x;
    const int tx = tid & 15, ty = tid >> 4;
    const int bm = blockIdx.y * 128, bn = blockIdx.x * 128;

    const int lr = tid >> 1;       // 0..127 : tile row loaded by this thread
    const int lk = (tid & 1) * 4;  // 0 or 4 : k-quad

    const float* Arow;
    {
        int m = bm + lr;
        int src = gather ? gather[m] : m;
        Arow = A + (size_t)src * K;
    }
    const float* Brow = B + (size_t)(bn + lr) * K;

    float acc[8][8];
#pragma unroll
    for (int i = 0; i < 8; ++i)
#pragma unroll
        for (int j = 0; j < 8; ++j) acc[i][j] = 0.f;

    for (int k0 = 0; k0 < K; k0 += 8) {
        float4 av = *(const float4*)(Arow + k0 + lk);
        float4 bv = *(const float4*)(Brow + k0 + lk);
        As[lk + 0][lr] = av.x; As[lk + 1][lr] = av.y;
        As[lk + 2][lr] = av.z; As[lk + 3][lr] = av.w;
        Bs[lk + 0][lr] = bv.x; Bs[lk + 1][lr] = bv.y;
        Bs[lk + 2][lr] = bv.z; Bs[lk + 3][lr] = bv.w;
        __syncthreads();
#pragma unroll
        for (int kk = 0; kk < 8; ++kk) {
            float4 a0 = *(const float4*)&As[kk][ty * 4];
            float4 a1 = *(const float4*)&As[kk][64 + ty * 4];
            float4 b0 = *(const float4*)&Bs[kk][tx * 4];
            float4 b1 = *(const float4*)&Bs[kk][64 + tx * 4];
            float af[8] = {a0.x, a0.y, a0.z, a0.w, a1.x, a1.y, a1.z, a1.w};
            float bf[8] = {b0.x, b0.y, b0.z, b0.w, b1.x, b1.y, b1.z, b1.w};
#pragma unroll
            for (int i = 0; i < 8; ++i)
#pragma unroll
                for (int jj = 0; jj < 8; ++jj)
                    acc[i][jj] += af[i] * bf[jj];
        }
        __syncthreads();
    }

#pragma unroll
    for (int i = 0; i < 8; ++i) {
        int row = bm + (i < 4 ? ty * 4 + i : 64 + ty * 4 + (i - 4));
#pragma unroll
        for (int jj = 0; jj < 8; ++jj) {
            int col = bn + (jj < 4 ? tx * 4 + jj : 64 + tx * 4 + (jj - 4));
            float v = acc[i][jj];
            if (bias1) v += bias1[col];
            if (bias2) v += bias2[col];
            C[(size_t)row * N + col] = v;
        }
    }
}

// =================================================================
// Persistent LSTM scan.
// 128 CTAs x 256 threads. Warp w of CTA b owns hidden unit
// j = b*8 + w: its 4 gate rows of W_hh live in that warp's registers
// (lane l holds columns l*4+128*i, i=0..7 -> 128 floats/lane).
// Per step: broadcast h through L2 (__ldcg; L1 is not coherent),
// 4 dot products + shfl reduction, cell update on lane 0 (c stays in
// a register the whole scan), write h to the ping-pong buffer,
// grid barrier (monotonic counters -> safe across graph replays).
// =================================================================
__global__ void __launch_bounds__(256, 1) lstm_scan_kernel(
    const float* __restrict__ h0, const float* __restrict__ c0,
    const float* __restrict__ W_hh, float* __restrict__ out_tail)
{
    __shared__ float sh[HH];
    const int tid  = threadIdx.x;
    const int w    = tid >> 5;
    const int lane = tid & 31;
    const int j    = blockIdx.x * UPC + w;

    // Weight preload into registers (coalesced 512B per (g,i) per warp)
    float4 wreg[4][8];
#pragma unroll
    for (int g = 0; g < 4; ++g)
#pragma unroll
        for (int i = 0; i < 8; ++i)
            wreg[g][i] = *(const float4*)(W_hh + (size_t)(g * HH + j) * HH
                                          + lane * 4 + 128 * i);

    float c_reg = c0[j];
    const unsigned relbase = *(volatile unsigned*)&g_release; // before 1st arrive

    for (int t = 0; t < TT; ++t) {
        const float* hsrc = (t == 0) ? h0 : g_hbuf[t & 1];
        float4 hv = __ldcg((const float4*)hsrc + tid);   // bypass stale L1
        *((float4*)sh + tid) = hv;
        __syncthreads();

        float4 hreg[8];
#pragma unroll
        for (int i = 0; i < 8; ++i)
            hreg[i] = *((const float4*)sh + lane + 32 * i);

        float gate[4];
#pragma unroll
        for (int g = 0; g < 4; ++g) {
            float s = 0.f;
#pragma unroll
            for (int i = 0; i < 8; ++i)
                s += wreg[g][i].x * hreg[i].x + wreg[g][i].y * hreg[i].y
                   + wreg[g][i].z * hreg[i].z + wreg[g][i].w * hreg[i].w;
#pragma unroll
            for (int o = 16; o; o >>= 1) s += __shfl_xor_sync(0xffffffffu, s, o);
            gate[g] = s;
        }

        if (lane == 0) {
            const float* xg = g_xg + (size_t)t * G4;
            float gi = gate[0] + xg[j];
            float gf = gate[1] + xg[HH + j];
            float gg = gate[2] + xg[2 * HH + j];
            float go = gate[3] + xg[3 * HH + j];
            float i_ = 1.f / (1.f + expf(-gi));
            float f_ = 1.f / (1.f + expf(-gf));
            float g_ = tanhf(gg);
            float o_ = 1.f / (1.f + expf(-go));
            c_reg = f_ * c_reg + i_ * g_;
            float h_ = o_ * tanhf(c_reg);
            g_hbuf[(t + 1) & 1][j] = h_;
            g_hs[(size_t)t * HH + j] = h_;
            if (t == TT - 1) { out_tail[j] = h_; out_tail[HH + j] = c_reg; }
        }

        // ---- grid barrier (release/acquire via L2 atomics) ----
        __threadfence();          // publish this CTA's h writes
        __syncthreads();          // all warps done before tid0 arrives
        if (tid == 0) {
            unsigned target = relbase + (unsigned)t + 1u;
            unsigned a = atomicAdd(&g_arrive, 1u);
            if ((a + 1u) % (unsigned)NCTA == 0u) {
                atomicAdd(&g_release, 1u);   // last arriver releases everyone
            } else {
                while ((int)(*(volatile unsigned*)&g_release - target) < 0) { }
            }
        }
        __syncthreads();
    }
}

// =================================================================
// Row log-softmax: one block per row of [T, V].
// =================================================================
__global__ void __launch_bounds__(256) logsoftmax_kernel(
    const float* __restrict__ scores, float* __restrict__ out)
{
    __shared__ float red[256];
    const int row = blockIdx.x;
    const int tid = threadIdx.x;
    const float* s = scores + (size_t)row * VV;

    float mx = -3.402823466e38f;
    for (int v = tid; v < VV; v += 256) mx = fmaxf(mx, s[v]);
    red[tid] = mx; __syncthreads();
    for (int st = 128; st > 0; st >>= 1) {
        if (tid < st) red[tid] = fmaxf(red[tid], red[tid + st]);
        __syncthreads();
    }
    mx = red[0]; __syncthreads();

    float sum = 0.f;
    for (int v = tid; v < VV; v += 256) sum += __expf(s[v] - mx);
    red[tid] = sum; __syncthreads();
    for (int st = 128; st > 0; st >>= 1) {
        if (tid < st) red[tid] += red[tid + st];
        __syncthreads();
    }
    float L = mx + logf(red[0]);

    float* o = out + (size_t)row * VV;
    for (int v = tid; v < VV; v += 256) o[v] = s[v] - L;
}

// =================================================================
extern "C" void kernel_launch(void* const* d_in, const int* in_sizes, int n_in,
                              void* d_out, int out_size)
{
    (void)in_sizes; (void)n_in; (void)out_size;
    const int*   seq   = (const int*)  d_in[0];
    const float* h0    = (const float*)d_in[1];
    const float* c0    = (const float*)d_in[2];
    const float* emb   = (const float*)d_in[3];
    const float* W_ih  = (const float*)d_in[4];
    const float* W_hh  = (const float*)d_in[5];
    const float* b_ih  = (const float*)d_in[6];
    const float* b_hh  = (const float*)d_in[7];
    const float* W_out = (const float*)d_in[8];
    const float* b_out = (const float*)d_in[9];
    float* out = (float*)d_out;

    float *p_xg = nullptr, *p_hs = nullptr, *p_scores = nullptr;
    cudaGetSymbolAddress((void**)&p_xg, g_xg);
    cudaGetSymbolAddress((void**)&p_hs, g_hs);
    cudaGetSymbolAddress((void**)&p_scores, g_scores);

    // 1) xg = emb[seq] @ W_ih^T + (b_ih + b_hh)     [T, 4H]
    {
        dim3 grid(G4 / 128, TT / 128);
        sgemm_tn<<<grid, 256>>>(emb, W_ih, b_ih, b_hh, p_xg, TT, G4, EE, seq);
    }
    // 2) sequential LSTM scan -> g_hs, hT/cT straight into d_out tail
    lstm_scan_kernel<<<NCTA, 256>>>(h0, c0, W_hh, out + (size_t)TT * VV);
    // 3) scores = hs @ W_out^T + b_out              [T, V]
    {
        dim3 grid(VV / 128, TT / 128);
        sgemm_tn<<<grid, 256>>>(p_hs, W_out, b_out, nullptr, p_scores,
                                TT, VV, HH, nullptr);
    }
    // 4) logp = log_softmax(scores)                 -> d_out
    logsoftmax_kernel<<<TT, 256>>>(p_scores, out);
}

// round 2
// speedup vs baseline: 1.4780x; 1.4780x over previous
#include <cuda_runtime.h>
#include <cuda_bf16.h>
#include <cstdint>
#include <cstddef>

// Problem constants
#define TT   2048
#define HH   1024
#define EE   1024
#define VV   32000
#define G4   4096
#define NCTA 128
#define UPC  8

// ---------------- scratch (no allocations allowed) ----------------
__device__ float g_xg[(size_t)TT * G4];                       // [T,4H] fp32
__device__ float g_scores[(size_t)TT * VV];                   // [T,V] fp32
__device__ __align__(16) __nv_bfloat16 g_x16[(size_t)TT * EE];        // gathered emb, bf16
__device__ __align__(16) __nv_bfloat16 g_wih16[(size_t)G4 * EE];      // W_ih bf16
__device__ __align__(16) __nv_bfloat16 g_wout16[(size_t)VV * HH];     // W_out bf16
__device__ __align__(16) __nv_bfloat16 g_hs16[(size_t)TT * HH];       // hs bf16
__device__ float g_hbuf[2][HH];
__device__ unsigned g_arrive;
__device__ unsigned g_release;

// ---------------- conversions ----------------
__global__ void gather_x16_kernel(const int* __restrict__ seq,
                                  const float* __restrict__ emb)
{
    int t = blockIdx.x;
    const float* src = emb + (size_t)seq[t] * EE;
    __nv_bfloat16* dst = g_x16 + (size_t)t * EE;
    for (int e = threadIdx.x; e < EE; e += blockDim.x)
        dst[e] = __float2bfloat16(src[e]);
}

__global__ void f2bf_kernel(const float* __restrict__ src,
                            __nv_bfloat16* __restrict__ dst, size_t n)
{
    size_t i = (size_t)blockIdx.x * blockDim.x + threadIdx.x;
    size_t stride = (size_t)gridDim.x * blockDim.x;
    for (; i < n; i += stride) dst[i] = __float2bfloat16(src[i]);
}

// =================================================================
// bf16 tensor-core GEMM: C[m][n] = sum_k A[m,k]*B[n,k] (+bias)
// Tile 128x128x32, 256 threads (8 warps in 2x4), mma.m16n8k16,
// double-buffered smem, ldmatrix loads. K % 32 == 0, dims % 128 == 0.
// =================================================================
#define SKP 40   // padded smem row stride (bf16 elems): 80B, conflict-free

__device__ __forceinline__ void ldsm_x4(uint32_t& r0, uint32_t& r1,
                                        uint32_t& r2, uint32_t& r3,
                                        const __nv_bfloat16* p)
{
    uint32_t addr = (uint32_t)__cvta_generic_to_shared(p);
    asm volatile("ldmatrix.sync.aligned.m8n8.x4.shared.b16 {%0,%1,%2,%3}, [%4];\n"
                 : "=r"(r0), "=r"(r1), "=r"(r2), "=r"(r3) : "r"(addr));
}

__device__ __forceinline__ void mma16816(float* d, const uint32_t* a,
                                         const uint32_t* b)
{
    asm volatile(
        "mma.sync.aligned.m16n8k16.row.col.f32.bf16.bf16.f32 "
        "{%0,%1,%2,%3}, {%4,%5,%6,%7}, {%8,%9}, {%0,%1,%2,%3};\n"
        : "+f"(d[0]), "+f"(d[1]), "+f"(d[2]), "+f"(d[3])
        : "r"(a[0]), "r"(a[1]), "r"(a[2]), "r"(a[3]), "r"(b[0]), "r"(b[1]));
}

__global__ void __launch_bounds__(256) bgemm_tn(
    const __nv_bfloat16* __restrict__ A, const __nv_bfloat16* __restrict__ B,
    const float* __restrict__ bias1, const float* __restrict__ bias2,
    float* __restrict__ C, int M, int N, int K)
{
    __shared__ __nv_bfloat16 Asm[2][128 * SKP];
    __shared__ __nv_bfloat16 Bsm[2][128 * SKP];

    const int tid = threadIdx.x;
    const int lane = tid & 31;
    const int w = tid >> 5;
    const int wm = w >> 2;            // 0..1 : 64-row slab
    const int wn = w & 3;             // 0..3 : 32-col slab
    const int bm = blockIdx.y * 128, bn = blockIdx.x * 128;

    // global load mapping: 2 chunks/thread/matrix; chunk -> (row, 8-col group)
    const int c0 = tid, c1 = tid + 256;
    const int r0g = c0 >> 2, k0g = (c0 & 3) * 8;
    const int r1g = c1 >> 2, k1g = (c1 & 3) * 8;
    const __nv_bfloat16* Ap0 = A + (size_t)(bm + r0g) * K + k0g;
    const __nv_bfloat16* Ap1 = A + (size_t)(bm + r1g) * K + k1g;
    const __nv_bfloat16* Bp0 = B + (size_t)(bn + r0g) * K + k0g;
    const __nv_bfloat16* Bp1 = B + (size_t)(bn + r1g) * K + k1g;

    float acc[4][4][4];
#pragma unroll
    for (int i = 0; i < 4; ++i)
#pragma unroll
        for (int j = 0; j < 4; ++j)
#pragma unroll
            for (int q = 0; q < 4; ++q) acc[i][j][q] = 0.f;

    // preload tile 0
    {
        float4 a0 = *(const float4*)Ap0;
        float4 a1 = *(const float4*)Ap1;
        float4 b0 = *(const float4*)Bp0;
        float4 b1 = *(const float4*)Bp1;
        *(float4*)&Asm[0][r0g * SKP + k0g] = a0;
        *(float4*)&Asm[0][r1g * SKP + k1g] = a1;
        *(float4*)&Bsm[0][r0g * SKP + k0g] = b0;
        *(float4*)&Bsm[0][r1g * SKP + k1g] = b1;
    }
    __syncthreads();

    const int KT = K / 32;
    for (int kt = 0; kt < KT; ++kt) {
        const int cur = kt & 1, nxt = cur ^ 1;
        float4 pa0, pa1, pb0, pb1;
        if (kt + 1 < KT) {
            int ko = (kt + 1) * 32;
            pa0 = *(const float4*)(Ap0 + ko);
            pa1 = *(const float4*)(Ap1 + ko);
            pb0 = *(const float4*)(Bp0 + ko);
            pb1 = *(const float4*)(Bp1 + ko);
        }

        const __nv_bfloat16* As = Asm[cur];
        const __nv_bfloat16* Bs = Bsm[cur];
#pragma unroll
        for (int ks = 0; ks < 2; ++ks) {
            uint32_t af[4][4];
#pragma unroll
            for (int mf = 0; mf < 4; ++mf)
                ldsm_x4(af[mf][0], af[mf][1], af[mf][2], af[mf][3],
                        &As[(wm * 64 + mf * 16 + (lane & 15)) * SKP
                            + ks * 16 + (lane >> 4) * 8]);
            uint32_t bf[4][2];
#pragma unroll
            for (int p = 0; p < 2; ++p) {
                uint32_t r0, r1, r2, r3;
                ldsm_x4(r0, r1, r2, r3,
                        &Bs[(wn * 32 + p * 16 + ((lane >> 4) << 3) + (lane & 7)) * SKP
                            + ks * 16 + ((lane >> 3) & 1) * 8]);
                bf[p * 2][0] = r0; bf[p * 2][1] = r1;
                bf[p * 2 + 1][0] = r2; bf[p * 2 + 1][1] = r3;
            }
#pragma unroll
            for (int mf = 0; mf < 4; ++mf)
#pragma unroll
                for (int nf = 0; nf < 4; ++nf)
                    mma16816(acc[mf][nf], af[mf], bf[nf]);
        }

        if (kt + 1 < KT) {
            *(float4*)&Asm[nxt][r0g * SKP + k0g] = pa0;
            *(float4*)&Asm[nxt][r1g * SKP + k1g] = pa1;
            *(float4*)&Bsm[nxt][r0g * SKP + k0g] = pb0;
            *(float4*)&Bsm[nxt][r1g * SKP + k1g] = pb1;
            __syncthreads();
        }
    }

    // epilogue
    const int gid = lane >> 2, tg = lane & 3;
#pragma unroll
    for (int mf = 0; mf < 4; ++mf) {
        int row0 = bm + wm * 64 + mf * 16 + gid;
#pragma unroll
        for (int nf = 0; nf < 4; ++nf) {
            int col = bn + wn * 32 + nf * 8 + tg * 2;
            float b0 = 0.f, b1 = 0.f;
            if (bias1) { b0 += bias1[col]; b1 += bias1[col + 1]; }
            if (bias2) { b0 += bias2[col]; b1 += bias2[col + 1]; }
            C[(size_t)row0 * N + col]           = acc[mf][nf][0] + b0;
            C[(size_t)row0 * N + col + 1]       = acc[mf][nf][1] + b1;
            C[(size_t)(row0 + 8) * N + col]     = acc[mf][nf][2] + b0;
            C[(size_t)(row0 + 8) * N + col + 1] = acc[mf][nf][3] + b1;
        }
    }
}

// =================================================================
// Persistent LSTM scan (unchanged math; emits bf16 hs)
// =================================================================
__global__ void __launch_bounds__(256, 1) lstm_scan_kernel(
    const float* __restrict__ h0, const float* __restrict__ c0,
    const float* __restrict__ W_hh, float* __restrict__ out_tail)
{
    __shared__ float sh[HH];
    const int tid  = threadIdx.x;
    const int w    = tid >> 5;
    const int lane = tid & 31;
    const int j    = blockIdx.x * UPC + w;

    float4 wreg[4][8];
#pragma unroll
    for (int g = 0; g < 4; ++g)
#pragma unroll
        for (int i = 0; i < 8; ++i)
            wreg[g][i] = *(const float4*)(W_hh + (size_t)(g * HH + j) * HH
                                          + lane * 4 + 128 * i);

    float c_reg = c0[j];
    const unsigned relbase = *(volatile unsigned*)&g_release;

    for (int t = 0; t < TT; ++t) {
        const float* hsrc = (t == 0) ? h0 : g_hbuf[t & 1];
        float4 hv = __ldcg((const float4*)hsrc + tid);
        *((float4*)sh + tid) = hv;
        __syncthreads();

        float4 hreg[8];
#pragma unroll
        for (int i = 0; i < 8; ++i)
            hreg[i] = *((const float4*)sh + lane + 32 * i);

        float gate[4];
#pragma unroll
        for (int g = 0; g < 4; ++g) {
            float s = 0.f;
#pragma unroll
            for (int i = 0; i < 8; ++i)
                s += wreg[g][i].x * hreg[i].x + wreg[g][i].y * hreg[i].y
                   + wreg[g][i].z * hreg[i].z + wreg[g][i].w * hreg[i].w;
#pragma unroll
            for (int o = 16; o; o >>= 1) s += __shfl_xor_sync(0xffffffffu, s, o);
            gate[g] = s;
        }

        if (lane == 0) {
            const float* xg = g_xg + (size_t)t * G4;
            float gi = gate[0] + xg[j];
            float gf = gate[1] + xg[HH + j];
            float gg = gate[2] + xg[2 * HH + j];
            float go = gate[3] + xg[3 * HH + j];
            float i_ = 1.f / (1.f + expf(-gi));
            float f_ = 1.f / (1.f + expf(-gf));
            float g_ = tanhf(gg);
            float o_ = 1.f / (1.f + expf(-go));
            c_reg = f_ * c_reg + i_ * g_;
            float h_ = o_ * tanhf(c_reg);
            g_hbuf[(t + 1) & 1][j] = h_;
            g_hs16[(size_t)t * HH + j] = __float2bfloat16(h_);
            if (t == TT - 1) { out_tail[j] = h_; out_tail[HH + j] = c_reg; }
        }

        __threadfence();
        __syncthreads();
        if (tid == 0) {
            unsigned target = relbase + (unsigned)t + 1u;
            unsigned a = atomicAdd(&g_arrive, 1u);
            if ((a + 1u) % (unsigned)NCTA == 0u) {
                atomicAdd(&g_release, 1u);
            } else {
                while ((int)(*(volatile unsigned*)&g_release - target) < 0) { }
            }
        }
        __syncthreads();
    }
}

// =================================================================
// Row log-softmax
// =================================================================
__global__ void __launch_bounds__(256) logsoftmax_kernel(
    const float* __restrict__ scores, float* __restrict__ out)
{
    __shared__ float red[256];
    const int row = blockIdx.x;
    const int tid = threadIdx.x;
    const float* s = scores + (size_t)row * VV;

    float mx = -3.402823466e38f;
    for (int v = tid; v < VV; v += 256) mx = fmaxf(mx, s[v]);
    red[tid] = mx; __syncthreads();
    for (int st = 128; st > 0; st >>= 1) {
        if (tid < st) red[tid] = fmaxf(red[tid], red[tid + st]);
        __syncthreads();
    }
    mx = red[0]; __syncthreads();

    float sum = 0.f;
    for (int v = tid; v < VV; v += 256) sum += __expf(s[v] - mx);
    red[tid] = sum; __syncthreads();
    for (int st = 128; st > 0; st >>= 1) {
        if (tid < st) red[tid] += red[tid + st];
        __syncthreads();
    }
    float L = mx + logf(red[0]);

    float* o = out + (size_t)row * VV;
    for (int v = tid; v < VV; v += 256) o[v] = s[v] - L;
}

// =================================================================
extern "C" void kernel_launch(void* const* d_in, const int* in_sizes, int n_in,
                              void* d_out, int out_size)
{
    (void)in_sizes; (void)n_in; (void)out_size;
    const int*   seq   = (const int*)  d_in[0];
    const float* h0    = (const float*)d_in[1];
    const float* c0    = (const float*)d_in[2];
    const float* emb   = (const float*)d_in[3];
    const float* W_ih  = (const float*)d_in[4];
    const float* W_hh  = (const float*)d_in[5];
    const float* b_ih  = (const float*)d_in[6];
    const float* b_hh  = (const float*)d_in[7];
    const float* W_out = (const float*)d_in[8];
    const float* b_out = (const float*)d_in[9];
    float* out = (float*)d_out;

    float *p_xg = nullptr, *p_scores = nullptr;
    __nv_bfloat16 *p_x16 = nullptr, *p_wih16 = nullptr, *p_wout16 = nullptr,
                  *p_hs16 = nullptr;
    cudaGetSymbolAddress((void**)&p_xg, g_xg);
    cudaGetSymbolAddress((void**)&p_scores, g_scores);
    cudaGetSymbolAddress((void**)&p_x16, g_x16);
    cudaGetSymbolAddress((void**)&p_wih16, g_wih16);
    cudaGetSymbolAddress((void**)&p_wout16, g_wout16);
    cudaGetSymbolAddress((void**)&p_hs16, g_hs16);

    // 0) conversions
    gather_x16_kernel<<<TT, 256>>>(seq, emb);
    f2bf_kernel<<<512, 256>>>(W_ih, p_wih16, (size_t)G4 * EE);
    f2bf_kernel<<<2048, 256>>>(W_out, p_wout16, (size_t)VV * HH);

    // 1) xg = x @ W_ih^T + (b_ih + b_hh)   [T, 4H]  (bf16 tensor cores)
    {
        dim3 grid(G4 / 128, TT / 128);
        bgemm_tn<<<grid, 256>>>(p_x16, p_wih16, b_ih, b_hh, p_xg, TT, G4, EE);
    }
    // 2) sequential LSTM scan -> g_hs16, hT/cT into d_out tail
    lstm_scan_kernel<<<NCTA, 256>>>(h0, c0, W_hh, out + (size_t)TT * VV);
    // 3) scores = hs @ W_out^T + b_out     [T, V]   (bf16 tensor cores)
    {
        dim3 grid(VV / 128, TT / 128);
        bgemm_tn<<<grid, 256>>>(p_hs16, p_wout16, b_out, nullptr, p_scores,
                                TT, VV, HH);
    }
    // 4) logp = log_softmax(scores) -> d_out
    logsoftmax_kernel<<<TT, 256>>>(p_scores, out);
}